// round 10
// baseline (speedup 1.0000x reference)
#include <cuda_runtime.h>
#include <cuda_fp16.h>
#include <cstdint>

// ---------------------------------------------------------------------------
// Problem constants
// ---------------------------------------------------------------------------
#define HH   4
#define HDm  256
#define Dm   1024
#define Sm   4096
#define Bm   8
#define MTOK (Bm * Sm)   // 32768 tokens
#define NDT  16          // d-tiles of 64

// Gate scratch, scan-native layout: [dtile][token][64d x 4 gates]. 512 MB fp32.
// Contiguous per (dtile, token): 1024 B; per scan block: 4 MB fully contiguous.
__device__ float g_g2[(size_t)NDT * MTOK * 256];
// fp16 copies of x and gate-interleaved W for cp.async streaming.
__device__ __half g_xh[(size_t)MTOK * Dm];            // 64 MB
__device__ __half g_wh[(size_t)HH * Dm * HDm];        // 2 MB: [h][n][k], n=o*4+g

__device__ __forceinline__ uint32_t smem_to_u32(const void* p) {
    uint32_t a;
    asm("{ .reg .u64 t; cvta.to.shared.u64 t, %1; cvt.u32.u64 %0, t; }" : "=r"(a) : "l"(p));
    return a;
}
__device__ __forceinline__ void cp_async16(uint32_t smem_addr, const void* gptr) {
    asm volatile("cp.async.cg.shared.global [%0], [%1], 16;"
                 :: "r"(smem_addr), "l"(gptr) : "memory");
}

// ---- mbarrier helpers ----
#define MBARRIER_INIT(addr, cnt) \
    asm volatile("mbarrier.init.shared.b64 [%0], %1;" :: "r"((uint32_t)(addr)), "r"((uint32_t)(cnt)) : "memory")
#define MBARRIER_EXPECT_TX(addr, bytes) \
    asm volatile("mbarrier.arrive.expect_tx.shared.b64 _, [%0], %1;" :: "r"((uint32_t)(addr)), "r"((uint32_t)(bytes)) : "memory")
#define MBARRIER_ARRIVE(addr) \
    asm volatile("mbarrier.arrive.shared.b64 _, [%0];" :: "r"((uint32_t)(addr)) : "memory")
#define MBARRIER_WAIT_PARITY(addr, par) do {                                       \
    uint32_t _m = (uint32_t)(addr); uint32_t _p = (uint32_t)(par); uint32_t _d;    \
    asm volatile("{\n\t.reg .pred p;\n\t"                                          \
        "mbarrier.try_wait.parity.acquire.cta.shared::cta.b64 p, [%1], %2;\n\t"    \
        "selp.b32 %0, 1, 0, p;\n\t}" : "=r"(_d) : "r"(_m), "r"(_p) : "memory");    \
    if (!_d) {                                                                     \
        asm volatile("{\n\t.reg .pred P1;\n\t"                                     \
            "WL_%=:\n\t"                                                           \
            "mbarrier.try_wait.parity.acquire.cta.shared::cta.b64 P1, [%0], %1, 0x989680;\n\t" \
            "@P1 bra.uni WD_%=;\n\t"                                               \
            "bra.uni WL_%=;\n\t"                                                   \
            "WD_%=:\n\t}" :: "r"(_m), "r"(_p) : "memory");                         \
    } } while (0)

__device__ __forceinline__ void cp_bulk(uint32_t smem_addr, const void* gptr,
                                        uint32_t bytes, uint32_t mbar) {
    asm volatile(
        "cp.async.bulk.shared::cluster.global.mbarrier::complete_tx::bytes [%0], [%1], %2, [%3];"
        :: "r"(smem_addr), "l"(gptr), "r"(bytes), "r"(mbar) : "memory");
}

// ---------------------------------------------------------------------------
// Preconvert: x -> fp16 (same layout), W -> fp16 gate-interleaved [h][n][k].
// ---------------------------------------------------------------------------
__global__ __launch_bounds__(256) void conv_x(const float* __restrict__ x)
{
    const size_t i = ((size_t)blockIdx.x * 256 + threadIdx.x) * 4;
    const float4 v = *(const float4*)(x + i);
    __half2 lo = __floats2half2_rn(v.x, v.y);
    __half2 hi = __floats2half2_rn(v.z, v.w);
    *(uint2*)(g_xh + i) = make_uint2(*(uint32_t*)&lo, *(uint32_t*)&hi);
}

__global__ __launch_bounds__(256) void conv_w(
    const float* __restrict__ Wz, const float* __restrict__ Wi,
    const float* __restrict__ Wf, const float* __restrict__ Wo)
{
    const size_t q = (size_t)blockIdx.x * 256 + threadIdx.x;   // float4 index
    const size_t j = q * 4;
    const int h = (int)(j >> 18);
    const int n = (int)((j >> 8) & 1023);
    const int k = (int)(j & 255);
    const int g = n & 3;
    const int o = n >> 2;
    const float* W = (g == 0) ? Wz : (g == 1) ? Wi : (g == 2) ? Wf : Wo;
    const float4 v = *(const float4*)&W[((size_t)(h * HDm + o)) * HDm + k];
    __half2 lo = __floats2half2_rn(v.x, v.y);
    __half2 hi = __floats2half2_rn(v.z, v.w);
    *(uint2*)(g_wh + j) = make_uint2(*(uint32_t*)&lo, *(uint32_t*)&hi);
}

// ---------------------------------------------------------------------------
// fp16 mma m16n8k16 + ldmatrix
// ---------------------------------------------------------------------------
__device__ __forceinline__ void mma_fp16(float c[4], const uint32_t a[4], const uint32_t b[2]) {
    asm volatile(
        "mma.sync.aligned.m16n8k16.row.col.f32.f16.f16.f32 "
        "{%0,%1,%2,%3}, {%4,%5,%6,%7}, {%8,%9}, {%0,%1,%2,%3};"
        : "+f"(c[0]), "+f"(c[1]), "+f"(c[2]), "+f"(c[3])
        : "r"(a[0]), "r"(a[1]), "r"(a[2]), "r"(a[3]), "r"(b[0]), "r"(b[1]));
}
__device__ __forceinline__ void ldsm_x4(uint32_t addr, uint32_t r[4]) {
    asm volatile("ldmatrix.sync.aligned.m8n8.x4.shared.b16 {%0,%1,%2,%3}, [%4];"
                 : "=r"(r[0]), "=r"(r[1]), "=r"(r[2]), "=r"(r[3]) : "r"(addr));
}

// ---------------------------------------------------------------------------
// Pregate GEMM (compute unchanged from R8 — fallback-HMMA ceiling ~24cyc/HMMA).
// Epilogue writes the scan-native layout.
// ---------------------------------------------------------------------------
#define BM 128
#define BN 128
#define BKH 32
#define NITER (HDm / BKH)       // 8
#define ROWB 80
#define STAGEB (256 * ROWB)     // 20480 B

__global__ __launch_bounds__(256, 2) void pregate_gemm(void)
{
    __shared__ __align__(16) char sm[3 * STAGEB];
    const uint32_t sbase = smem_to_u32(sm);

    const int tid  = threadIdx.x;
    const int lane = tid & 31;
    const int wid  = tid >> 5;
    const int wm   = wid & 1;
    const int wn   = wid >> 1;
    const int grp  = lane >> 2;
    const int tig  = lane & 3;

    const int n0 = blockIdx.x * BN;
    const int m0 = blockIdx.y * BM;
    const int h  = blockIdx.z;

    const int arr  = tid >> 7;
    const int row  = tid & 127;
    const __half* gsrc = arr
        ? (g_wh + ((size_t)(h * Dm + n0 + row)) * HDm)
        : (g_xh + (size_t)(m0 + row) * Dm + h * HDm);
    const uint32_t sdst = sbase + (uint32_t)tid * ROWB;

    uint32_t a_off[4], b_off[2];
    #pragma unroll
    for (int mf = 0; mf < 4; mf++)
        a_off[mf] = (uint32_t)((wm * 64 + mf * 16 + (lane & 15)) * ROWB + ((lane >> 4) * 8) * 2);
    #pragma unroll
    for (int p = 0; p < 2; p++)
        b_off[p] = (uint32_t)((128 + wn * 32 + p * 16 + ((lane >> 4) & 1) * 8 + (lane & 7)) * ROWB
                              + (((lane >> 3) & 1) * 8) * 2);

    float acc[4][4][4];
    #pragma unroll
    for (int mf = 0; mf < 4; mf++)
        #pragma unroll
        for (int nf = 0; nf < 4; nf++)
            #pragma unroll
            for (int i = 0; i < 4; i++) acc[mf][nf][i] = 0.0f;

    #pragma unroll
    for (int s = 0; s < 2; s++) {
        #pragma unroll
        for (int j = 0; j < 4; j++)
            cp_async16(sdst + s * STAGEB + j * 16, gsrc + s * BKH + j * 8);
        asm volatile("cp.async.commit_group;" ::: "memory");
    }

    #pragma unroll 1
    for (int it = 0; it < NITER; it++) {
        if (it < NITER - 1) asm volatile("cp.async.wait_group 1;" ::: "memory");
        else                asm volatile("cp.async.wait_group 0;" ::: "memory");
        __syncthreads();

        if (it + 2 < NITER) {
            const uint32_t so = (uint32_t)((it + 2) % 3) * STAGEB;
            const __half* gp = gsrc + (it + 2) * BKH;
            #pragma unroll
            for (int j = 0; j < 4; j++)
                cp_async16(sdst + so + j * 16, gp + j * 8);
            asm volatile("cp.async.commit_group;" ::: "memory");
        }

        const uint32_t stg = sbase + (uint32_t)(it % 3) * STAGEB;
        #pragma unroll
        for (int kk = 0; kk < 2; kk++) {
            const uint32_t ko = (uint32_t)(kk * 32);
            uint32_t a[4][4], b[2][4];
            #pragma unroll
            for (int mf = 0; mf < 4; mf++) ldsm_x4(stg + a_off[mf] + ko, a[mf]);
            #pragma unroll
            for (int p = 0; p < 2; p++)    ldsm_x4(stg + b_off[p] + ko, b[p]);
            #pragma unroll
            for (int mf = 0; mf < 4; mf++)
                #pragma unroll
                for (int nf = 0; nf < 4; nf++)
                    mma_fp16(acc[mf][nf], a[mf], &b[nf >> 1][(nf & 1) * 2]);
        }
    }

    // ---- epilogue: scan-native layout.
    // col = n0 + wn*32 + nf*8 + 2*tig; o = col>>2; d = h*256+o;
    // addr(floats) = ((dtile*MTOK + r) * 256) + (d&63)*4 + (col&3)
    const int gsub = (tig & 1) * 2;          // col & 3
    const int obase = (n0 >> 2) + wn * 8 + (tig >> 1);
    #pragma unroll
    for (int mf = 0; mf < 4; mf++) {
        const int r = m0 + wm * 64 + mf * 16 + grp;
        #pragma unroll
        for (int nf = 0; nf < 4; nf++) {
            const int d  = h * HDm + obase + nf * 2;
            const int dt = d >> 6;
            const int dd = d & 63;
            float* fp = g_g2 + ((size_t)dt * MTOK + r) * 256 + dd * 4 + gsub;
            *(float2*)fp             = make_float2(acc[mf][nf][0], acc[mf][nf][1]);
            *(float2*)(fp + 8 * 256) = make_float2(acc[mf][nf][2], acc[mf][nf][3]);
        }
    }
}

// ---------------------------------------------------------------------------
// Sequential scan: 128 blocks (b x dtile) x 128 threads.
// tid 0..63 compute; tid 64 producer issuing 4 x 16KB contiguous bulk copies
// per 64-step chunk (gate stream is fully contiguous in the new layout).
// NBUF=3 x 64KB ring, mbarrier full/empty.
// ---------------------------------------------------------------------------
#define CH    64
#define NBUF  3
#define NCH   (Sm / CH)                   // 64
#define CHBYTES (CH * 1024)               // 65536
#define MB_FULL(i)  (mb_base + (i) * 8)
#define MB_EMPTY(i) (mb_base + 24 + (i) * 8)
#define SCAN_SMEM (1024 + NBUF * CHBYTES) // 197632 B

__global__ __launch_bounds__(128) void slstm_scan(float* __restrict__ out)
{
    extern __shared__ __align__(16) char smem[];
    const uint32_t mb_base = smem_to_u32(smem);
    float4* sdata = (float4*)(smem + 1024);
    const uint32_t sdata_u32 = mb_base + 1024;

    const int tid = threadIdx.x;
    const int b   = blockIdx.x >> 4;             // 8 batches x 16 d-tiles
    const int dt  = blockIdx.x & 15;
    const size_t tb = (size_t)b * Sm;
    const float L2E = 1.4426950408889634f;

    if (tid == 0) {
        #pragma unroll
        for (int i = 0; i < NBUF; i++) {
            MBARRIER_INIT(MB_FULL(i), 1);
            MBARRIER_INIT(MB_EMPTY(i), 64);
        }
    }
    __syncthreads();

    if (tid == 64) {
        // ---- producer: 4 contiguous 16KB bulk copies per chunk ----
        const char* src0 = (const char*)(g_g2 + ((size_t)dt * MTOK + tb) * 256);
        int stage = 0, ph = 1;
        #pragma unroll 1
        for (int ck = 0; ck < NCH; ck++) {
            MBARRIER_WAIT_PARITY(MB_EMPTY(stage), ph);
            MBARRIER_EXPECT_TX(MB_FULL(stage), CHBYTES);
            const char* src = src0 + (size_t)ck * CHBYTES;
            const uint32_t dst = sdata_u32 + (uint32_t)stage * CHBYTES;
            #pragma unroll
            for (int j = 0; j < 4; j++)
                cp_bulk(dst + j * 16384, src + j * 16384, 16384, MB_FULL(stage));
            if (++stage == NBUF) { stage = 0; ph ^= 1; }
        }
    } else if (tid < 64) {
        // ---- consumer ----
        float c = 0.0f, n = 0.0f, m = 0.0f;
        float* orow = out + tb * Dm + dt * 64 + tid;
        int stage = 0, ph = 0;
        #pragma unroll 1
        for (int ck = 0; ck < NCH; ck++) {
            MBARRIER_WAIT_PARITY(MB_FULL(stage), ph);
            const float4* buf = sdata + stage * (CHBYTES / 16);
            float* op = orow + (size_t)ck * CH * Dm;
            #pragma unroll 4
            for (int j = 0; j < CH; j++) {
                const float4 gv = buf[j * 64 + tid];
                const float zt = gv.x, it_ = gv.y, ft = gv.z, ot = gv.w;

                const float fm = ft + m;
                const bool  fge = (fm >= it_);
                float e_;
                asm("ex2.approx.f32 %0, %1;" : "=f"(e_) : "f"(-fabsf(fm - it_) * L2E));
                const float i_hat = fge ? e_ : 1.0f;
                const float f_hat = fge ? 1.0f : e_;
                m = fmaxf(fm, it_);

                float z;
                asm("tanh.approx.f32 %0, %1;" : "=f"(z) : "f"(zt));
                float eo;
                asm("ex2.approx.f32 %0, %1;" : "=f"(eo) : "f"(-ot * L2E));

                c = f_hat * c + i_hat * z;
                n = f_hat * n + i_hat;

                const float den = (1.0f + eo) * (n + 1e-8f);
                float r_;
                asm("rcp.approx.f32 %0, %1;" : "=f"(r_) : "f"(den));
                op[(size_t)j * Dm] = c * r_;
            }
            MBARRIER_ARRIVE(MB_EMPTY(stage));
            if (++stage == NBUF) { stage = 0; ph ^= 1; }
        }
    }
}

// ---------------------------------------------------------------------------
extern "C" void kernel_launch(void* const* d_in, const int* in_sizes, int n_in,
                              void* d_out, int out_size)
{
    const float* x  = (const float*)d_in[0];
    const float* Wz = (const float*)d_in[1];
    const float* Wi = (const float*)d_in[2];
    const float* Wf = (const float*)d_in[3];
    const float* Wo = (const float*)d_in[4];
    float* out = (float*)d_out;

    conv_x<<<(MTOK * Dm / 4) / 256, 256>>>(x);
    conv_w<<<(HH * Dm * HDm / 4) / 256, 256>>>(Wz, Wi, Wf, Wo);

    dim3 grid(Dm / BN, MTOK / BM, HH);   // (8, 256, 4)
    pregate_gemm<<<grid, 256>>>();

    cudaFuncSetAttribute(slstm_scan, cudaFuncAttributeMaxDynamicSharedMemorySize, SCAN_SMEM);
    slstm_scan<<<128, 128, SCAN_SMEM>>>(out);
}

// round 14
// speedup vs baseline: 1.5293x; 1.5293x over previous
#include <cuda_runtime.h>
#include <cuda_fp16.h>
#include <cstdint>

// ---------------------------------------------------------------------------
// Problem constants
// ---------------------------------------------------------------------------
#define HH   4
#define HDm  256
#define Dm   1024
#define Sm   4096
#define Bm   8
#define MTOK (Bm * Sm)   // 32768 tokens

// Gate scratch: fp32 RAW gates (z,i,f,o) interleaved per (token, d). 512 MB.
__device__ float4 g_gates[(size_t)MTOK * Dm];
// fp16 copies of x and gate-interleaved W for cp.async streaming.
__device__ __half g_xh[(size_t)MTOK * Dm];            // 64 MB
__device__ __half g_wh[(size_t)HH * Dm * HDm];        // 2 MB: [h][n][k], n=o*4+g

#define L2E 1.4426950408889634f

__device__ __forceinline__ uint32_t smem_to_u32(const void* p) {
    uint32_t a;
    asm("{ .reg .u64 t; cvta.to.shared.u64 t, %1; cvt.u32.u64 %0, t; }" : "=r"(a) : "l"(p));
    return a;
}
__device__ __forceinline__ void cp_async16(uint32_t smem_addr, const void* gptr) {
    asm volatile("cp.async.cg.shared.global [%0], [%1], 16;"
                 :: "r"(smem_addr), "l"(gptr) : "memory");
}
__device__ __forceinline__ float mexp(float x) {
    float r; asm("ex2.approx.f32 %0, %1;" : "=f"(r) : "f"(x * L2E)); return r;
}
__device__ __forceinline__ float mtanh(float x) {
    float r; asm("tanh.approx.f32 %0, %1;" : "=f"(r) : "f"(x)); return r;
}
__device__ __forceinline__ float mrcp(float x) {
    float r; asm("rcp.approx.f32 %0, %1;" : "=f"(r) : "f"(x)); return r;
}

// ---- mbarrier helpers ----
#define MBARRIER_INIT(addr, cnt) \
    asm volatile("mbarrier.init.shared.b64 [%0], %1;" :: "r"((uint32_t)(addr)), "r"((uint32_t)(cnt)) : "memory")
#define MBARRIER_EXPECT_TX(addr, bytes) \
    asm volatile("mbarrier.arrive.expect_tx.shared.b64 _, [%0], %1;" :: "r"((uint32_t)(addr)), "r"((uint32_t)(bytes)) : "memory")
#define MBARRIER_ARRIVE(addr) \
    asm volatile("mbarrier.arrive.shared.b64 _, [%0];" :: "r"((uint32_t)(addr)) : "memory")
#define MBARRIER_WAIT_PARITY(addr, par) do {                                       \
    uint32_t _m = (uint32_t)(addr); uint32_t _p = (uint32_t)(par); uint32_t _d;    \
    asm volatile("{\n\t.reg .pred p;\n\t"                                          \
        "mbarrier.try_wait.parity.acquire.cta.shared::cta.b64 p, [%1], %2;\n\t"    \
        "selp.b32 %0, 1, 0, p;\n\t}" : "=r"(_d) : "r"(_m), "r"(_p) : "memory");    \
    if (!_d) {                                                                     \
        asm volatile("{\n\t.reg .pred P1;\n\t"                                     \
            "WL_%=:\n\t"                                                           \
            "mbarrier.try_wait.parity.acquire.cta.shared::cta.b64 P1, [%0], %1, 0x989680;\n\t" \
            "@P1 bra.uni WD_%=;\n\t"                                               \
            "bra.uni WL_%=;\n\t"                                                   \
            "WD_%=:\n\t}" :: "r"(_m), "r"(_p) : "memory");                         \
    } } while (0)

__device__ __forceinline__ void cp_bulk(uint32_t smem_addr, const void* gptr,
                                        uint32_t bytes, uint32_t mbar) {
    asm volatile(
        "cp.async.bulk.shared::cluster.global.mbarrier::complete_tx::bytes [%0], [%1], %2, [%3];"
        :: "r"(smem_addr), "l"(gptr), "r"(bytes), "r"(mbar) : "memory");
}

// ---------------------------------------------------------------------------
// Preconvert: x -> fp16 (same layout), W -> fp16 gate-interleaved [h][n][k].
// ---------------------------------------------------------------------------
__global__ __launch_bounds__(256) void conv_x(const float* __restrict__ x)
{
    const size_t i = ((size_t)blockIdx.x * 256 + threadIdx.x) * 4;
    const float4 v = *(const float4*)(x + i);
    __half2 lo = __floats2half2_rn(v.x, v.y);
    __half2 hi = __floats2half2_rn(v.z, v.w);
    *(uint2*)(g_xh + i) = make_uint2(*(uint32_t*)&lo, *(uint32_t*)&hi);
}

__global__ __launch_bounds__(256) void conv_w(
    const float* __restrict__ Wz, const float* __restrict__ Wi,
    const float* __restrict__ Wf, const float* __restrict__ Wo)
{
    const size_t q = (size_t)blockIdx.x * 256 + threadIdx.x;   // float4 index
    const size_t j = q * 4;
    const int h = (int)(j >> 18);
    const int n = (int)((j >> 8) & 1023);
    const int k = (int)(j & 255);
    const int g = n & 3;
    const int o = n >> 2;
    const float* W = (g == 0) ? Wz : (g == 1) ? Wi : (g == 2) ? Wf : Wo;
    const float4 v = *(const float4*)&W[((size_t)(h * HDm + o)) * HDm + k];
    __half2 lo = __floats2half2_rn(v.x, v.y);
    __half2 hi = __floats2half2_rn(v.z, v.w);
    *(uint2*)(g_wh + j) = make_uint2(*(uint32_t*)&lo, *(uint32_t*)&hi);
}

// ---------------------------------------------------------------------------
// fp16 mma m16n8k16 + ldmatrix
// ---------------------------------------------------------------------------
__device__ __forceinline__ void mma_fp16(float c[4], const uint32_t a[4], const uint32_t b[2]) {
    asm volatile(
        "mma.sync.aligned.m16n8k16.row.col.f32.f16.f16.f32 "
        "{%0,%1,%2,%3}, {%4,%5,%6,%7}, {%8,%9}, {%0,%1,%2,%3};"
        : "+f"(c[0]), "+f"(c[1]), "+f"(c[2]), "+f"(c[3])
        : "r"(a[0]), "r"(a[1]), "r"(a[2]), "r"(a[3]), "r"(b[0]), "r"(b[1]));
}
__device__ __forceinline__ void ldsm_x4(uint32_t addr, uint32_t r[4]) {
    asm volatile("ldmatrix.sync.aligned.m8n8.x4.shared.b16 {%0,%1,%2,%3}, [%4];"
                 : "=r"(r[0]), "=r"(r[1]), "=r"(r[2]), "=r"(r[3]) : "r"(addr));
}

// ---------------------------------------------------------------------------
// Pregate GEMM — R9 verbatim (raw gate stores; known-good at the 632us pass).
// ---------------------------------------------------------------------------
#define BM 128
#define BN 128
#define BKH 32
#define NITER (HDm / BKH)       // 8
#define ROWB 80
#define STAGEB (256 * ROWB)     // 20480 B

__global__ __launch_bounds__(256, 2) void pregate_gemm(void)
{
    __shared__ __align__(16) char sm[3 * STAGEB];
    const uint32_t sbase = smem_to_u32(sm);

    const int tid  = threadIdx.x;
    const int lane = tid & 31;
    const int wid  = tid >> 5;
    const int wm   = wid & 1;
    const int wn   = wid >> 1;
    const int grp  = lane >> 2;
    const int tig  = lane & 3;

    const int n0 = blockIdx.x * BN;
    const int m0 = blockIdx.y * BM;
    const int h  = blockIdx.z;

    const int arr  = tid >> 7;
    const int row  = tid & 127;
    const __half* gsrc = arr
        ? (g_wh + ((size_t)(h * Dm + n0 + row)) * HDm)
        : (g_xh + (size_t)(m0 + row) * Dm + h * HDm);
    const uint32_t sdst = sbase + (uint32_t)tid * ROWB;

    uint32_t a_off[4], b_off[2];
    #pragma unroll
    for (int mf = 0; mf < 4; mf++)
        a_off[mf] = (uint32_t)((wm * 64 + mf * 16 + (lane & 15)) * ROWB + ((lane >> 4) * 8) * 2);
    #pragma unroll
    for (int p = 0; p < 2; p++)
        b_off[p] = (uint32_t)((128 + wn * 32 + p * 16 + ((lane >> 4) & 1) * 8 + (lane & 7)) * ROWB
                              + (((lane >> 3) & 1) * 8) * 2);

    float acc[4][4][4];
    #pragma unroll
    for (int mf = 0; mf < 4; mf++)
        #pragma unroll
        for (int nf = 0; nf < 4; nf++)
            #pragma unroll
            for (int i = 0; i < 4; i++) acc[mf][nf][i] = 0.0f;

    #pragma unroll
    for (int s = 0; s < 2; s++) {
        #pragma unroll
        for (int j = 0; j < 4; j++)
            cp_async16(sdst + s * STAGEB + j * 16, gsrc + s * BKH + j * 8);
        asm volatile("cp.async.commit_group;" ::: "memory");
    }

    #pragma unroll 1
    for (int it = 0; it < NITER; it++) {
        if (it < NITER - 1) asm volatile("cp.async.wait_group 1;" ::: "memory");
        else                asm volatile("cp.async.wait_group 0;" ::: "memory");
        __syncthreads();

        if (it + 2 < NITER) {
            const uint32_t so = (uint32_t)((it + 2) % 3) * STAGEB;
            const __half* gp = gsrc + (it + 2) * BKH;
            #pragma unroll
            for (int j = 0; j < 4; j++)
                cp_async16(sdst + so + j * 16, gp + j * 8);
            asm volatile("cp.async.commit_group;" ::: "memory");
        }

        const uint32_t stg = sbase + (uint32_t)(it % 3) * STAGEB;
        #pragma unroll
        for (int kk = 0; kk < 2; kk++) {
            const uint32_t ko = (uint32_t)(kk * 32);
            uint32_t a[4][4], b[2][4];
            #pragma unroll
            for (int mf = 0; mf < 4; mf++) ldsm_x4(stg + a_off[mf] + ko, a[mf]);
            #pragma unroll
            for (int p = 0; p < 2; p++)    ldsm_x4(stg + b_off[p] + ko, b[p]);
            #pragma unroll
            for (int mf = 0; mf < 4; mf++)
                #pragma unroll
                for (int nf = 0; nf < 4; nf++)
                    mma_fp16(acc[mf][nf], a[mf], &b[nf >> 1][(nf & 1) * 2]);
        }
    }

    // ---- epilogue: RAW gate stores (R9 verbatim) ----
    float* gbuf = (float*)g_gates;
    #pragma unroll
    for (int mf = 0; mf < 4; mf++) {
        const int r = m0 + wm * 64 + mf * 16 + grp;
        float* orow = gbuf + (size_t)r * 4096 + h * 1024;
        #pragma unroll
        for (int nf = 0; nf < 4; nf++) {
            const int col = n0 + wn * 32 + nf * 8 + 2 * tig;
            *(float2*)&orow[col]                    = make_float2(acc[mf][nf][0], acc[mf][nf][1]);
            *(float2*)&orow[col + (size_t)8 * 4096] = make_float2(acc[mf][nf][2], acc[mf][nf][3]);
        }
    }
}

// ---------------------------------------------------------------------------
// Sequential scan — R9 structure and MATH verbatim; consumer restructured for
// ILP only: per 8-step group, batch the carry-INDEPENDENT loads + MUFUs
// (tanh z, exp -o) first, then run the 8 serial carry steps. Identical ops on
// identical values (no re-association) -> bit-identical output to the R9 pass.
// R9's consumer compiled to regs=32 (zero lookahead, ~105 cyc/step); this
// gives ptxas registers and independent MUFUs to pipeline the 16-cyc ex2.
// ---------------------------------------------------------------------------
#define CH    64
#define NBUF  3
#define NCH   (Sm / CH)                   // 64
#define CHBYTES (CH * 64 * 16)            // 65536
#define MB_FULL(i)  (mb_base + (i) * 8)
#define MB_EMPTY(i) (mb_base + 24 + (i) * 8)
#define SCAN_SMEM (1024 + NBUF * CHBYTES) // 197632 B

__global__ __launch_bounds__(128) void slstm_scan(float* __restrict__ out)
{
    extern __shared__ __align__(16) char smem[];
    const uint32_t mb_base = smem_to_u32(smem);
    float4* sdata = (float4*)(smem + 1024);
    const uint32_t sdata_u32 = mb_base + 1024;

    const int tid = threadIdx.x;
    const int b   = blockIdx.x >> 4;             // 8 batches x 16 d-tiles of 64
    const int d0  = (blockIdx.x & 15) * 64;
    const size_t tb = (size_t)b * Sm;

    if (tid == 0) {
        #pragma unroll
        for (int i = 0; i < NBUF; i++) {
            MBARRIER_INIT(MB_FULL(i), 1);
            MBARRIER_INIT(MB_EMPTY(i), 64);
        }
    }
    __syncthreads();

    if (tid == 64) {
        // ---- producer: 64 x 1KB bulk copies per 64-step chunk (R9 verbatim) ----
        int stage = 0, ph = 1;
        #pragma unroll 1
        for (int ck = 0; ck < NCH; ck++) {
            MBARRIER_WAIT_PARITY(MB_EMPTY(stage), ph);
            MBARRIER_EXPECT_TX(MB_FULL(stage), CHBYTES);
            const float4* src = g_gates + (tb + (size_t)ck * CH) * Dm + d0;
            const uint32_t dst = sdata_u32 + (uint32_t)stage * CHBYTES;
            #pragma unroll 4
            for (int j = 0; j < CH; j++)
                cp_bulk(dst + (uint32_t)j * 1024, src + (size_t)j * Dm, 1024, MB_FULL(stage));
            if (++stage == NBUF) { stage = 0; ph ^= 1; }
        }
    } else if (tid < 64) {
        // ---- consumer: R9 stabilized math, software-pipelined ----
        float c = 0.0f, n = 0.0f, m = 0.0f;
        float* orow = out + tb * Dm + d0 + tid;
        int stage = 0, ph = 0;
        #pragma unroll 1
        for (int ck = 0; ck < NCH; ck++) {
            MBARRIER_WAIT_PARITY(MB_FULL(stage), ph);
            const float4* buf = sdata + stage * (CHBYTES / 16);
            float* op = orow + (size_t)ck * CH * Dm;
            #pragma unroll 1
            for (int jj = 0; jj < CH; jj += 8) {
                // Phase A: carry-independent loads + MUFUs for 8 steps (batched)
                float4 g[8];
                float zp[8], eo[8];
                #pragma unroll
                for (int q = 0; q < 8; q++) {
                    g[q]  = buf[(jj + q) * 64 + tid];
                    zp[q] = mtanh(g[q].x);        // tanh(zt)
                    eo[q] = mexp(-g[q].w);        // e^{-ot}
                }
                // Phase B: serial carry chain (math identical to R9)
                #pragma unroll
                for (int q = 0; q < 8; q++) {
                    const float it_ = g[q].y, ft = g[q].z;
                    const float fm  = ft + m;
                    const bool  fge = (fm >= it_);
                    const float e_  = mexp(-fabsf(fm - it_));
                    const float i_hat = fge ? e_ : 1.0f;
                    const float f_hat = fge ? 1.0f : e_;
                    m = fmaxf(fm, it_);

                    c = fmaf(f_hat, c, i_hat * zp[q]);
                    n = fmaf(f_hat, n, i_hat);

                    const float den = (1.0f + eo[q]) * (n + 1e-8f);
                    op[(size_t)(jj + q) * Dm] = c * mrcp(den);
                }
            }
            MBARRIER_ARRIVE(MB_EMPTY(stage));
            if (++stage == NBUF) { stage = 0; ph ^= 1; }
        }
    }
}

// ---------------------------------------------------------------------------
extern "C" void kernel_launch(void* const* d_in, const int* in_sizes, int n_in,
                              void* d_out, int out_size)
{
    const float* x  = (const float*)d_in[0];
    const float* Wz = (const float*)d_in[1];
    const float* Wi = (const float*)d_in[2];
    const float* Wf = (const float*)d_in[3];
    const float* Wo = (const float*)d_in[4];
    float* out = (float*)d_out;

    conv_x<<<(MTOK * Dm / 4) / 256, 256>>>(x);
    conv_w<<<(HH * Dm * HDm / 4) / 256, 256>>>(Wz, Wi, Wf, Wo);

    dim3 grid(Dm / BN, MTOK / BM, HH);   // (8, 256, 4)
    pregate_gemm<<<grid, 256>>>();

    cudaFuncSetAttribute(slstm_scan, cudaFuncAttributeMaxDynamicSharedMemorySize, SCAN_SMEM);
    slstm_scan<<<128, 128, SCAN_SMEM>>>(out);
}